// round 1
// baseline (speedup 1.0000x reference)
#include <cuda_runtime.h>
#include <math.h>

// Problem constants
#define T_LEN 256
#define B_DIM 512
#define F_DIM 256
#define H_DIM 512
#define P_INT 12
#define KTOT  768   // F + H
#define NG    2048  // 4 * H (gates f,i,o,g concatenated)

// ---------------- static device scratch (no allocations allowed) ----------------
__device__ float d_Wcat[KTOT * NG];                 // packed weights [768][2048]
__device__ float d_Bcat[NG];                        // packed biases  [2048]
__device__ float d_Hbuf[P_INT * B_DIM * H_DIM];     // h ring buffer [12][512][512]
__device__ float d_Sbuf[P_INT * B_DIM * NG];        // wave gate pre-activations [6144][2048]
__device__ float d_Vbuf[P_INT * H_DIM];             // per-step c-row v for current wave
__device__ float d_Vcarry[H_DIM];                   // v carried across waves

// ---------------- pack: Wcat[k][g*H+h] = W_g[k][h], Bcat[g*H+h] = b_g[h] ----------------
__global__ void pack_kernel(const float* __restrict__ Wf, const float* __restrict__ bf,
                            const float* __restrict__ Wi, const float* __restrict__ bi,
                            const float* __restrict__ Wo, const float* __restrict__ bo,
                            const float* __restrict__ Wg, const float* __restrict__ bg) {
    int idx = blockIdx.x * blockDim.x + threadIdx.x;
    if (idx < KTOT * NG) {
        int k = idx / NG;
        int n = idx % NG;
        int g = n / H_DIM;
        int h = n % H_DIM;
        const float* W = (g == 0) ? Wf : (g == 1) ? Wi : (g == 2) ? Wo : Wg;
        d_Wcat[idx] = W[k * H_DIM + h];
    }
    if (idx < NG) {
        int g = idx / H_DIM, h = idx % H_DIM;
        const float* bb = (g == 0) ? bf : (g == 1) ? bi : (g == 2) ? bo : bg;
        d_Bcat[idx] = bb[h];
    }
}

// ---------------- init: zero h state and v carry (must be per-call deterministic) ----------------
__global__ void init_kernel() {
    int i = blockIdx.x * blockDim.x + threadIdx.x;
    if (i < P_INT * B_DIM * H_DIM) d_Hbuf[i] = 0.0f;
    if (i < H_DIM) d_Vcarry[i] = 0.0f;
}

// ---------------- wave GEMM: Sbuf[m][n] = sum_k A(m,k)*Wcat[k][n] + Bcat[n] ----------------
// A(m,k) = (k < F) ? X[(t0*B + m)*F + k] : Hbuf[m*H + (k-F)]
// M = nsteps*512 (multiple of 128), N = 2048, K = 768.
#define BM 128
#define BN 128
#define BK 8

__global__ void __launch_bounds__(256) gemm_wave(const float* __restrict__ X, int t0) {
    __shared__ float As[BK][BM];
    __shared__ float Bs[BK][BN];

    const int m0 = blockIdx.y * BM;
    const int n0 = blockIdx.x * BN;
    const int tid = threadIdx.x;

    // A-tile loader mapping: 128 rows x 8 k, 4 floats per thread
    const int arow = tid >> 1;          // 0..127
    const int akq  = (tid & 1) * 4;     // 0 or 4
    // B-tile loader mapping: 8 k x 128 n, float4 per thread
    const int bk   = tid >> 5;          // 0..7
    const int bnq  = (tid & 31) * 4;    // 0..124

    const int ty = tid >> 4;            // 0..15
    const int tx = tid & 15;            // 0..15

    float acc[8][8];
    #pragma unroll
    for (int i = 0; i < 8; i++)
        #pragma unroll
        for (int j = 0; j < 8; j++) acc[i][j] = 0.0f;

    const float* Xbase = X + (size_t)(t0 * B_DIM) * F_DIM;
    const int m = m0 + arow;

    for (int k0 = 0; k0 < KTOT; k0 += BK) {
        // load A tile (split source: x for k<256, Hbuf for k>=256)
        int k = k0 + akq;
        float4 av;
        if (k < F_DIM) {
            av = *(const float4*)(Xbase + (size_t)m * F_DIM + k);
        } else {
            av = *(const float4*)(d_Hbuf + (size_t)m * H_DIM + (k - F_DIM));
        }
        As[akq + 0][arow] = av.x;
        As[akq + 1][arow] = av.y;
        As[akq + 2][arow] = av.z;
        As[akq + 3][arow] = av.w;

        // load B tile
        float4 bv = *(const float4*)(d_Wcat + (size_t)(k0 + bk) * NG + n0 + bnq);
        *(float4*)(&Bs[bk][bnq]) = bv;

        __syncthreads();

        #pragma unroll
        for (int kk = 0; kk < BK; kk++) {
            float a[8], b[8];
            #pragma unroll
            for (int i = 0; i < 8; i++) a[i] = As[kk][ty * 8 + i];
            #pragma unroll
            for (int j = 0; j < 8; j++) b[j] = Bs[kk][tx * 8 + j];
            #pragma unroll
            for (int i = 0; i < 8; i++)
                #pragma unroll
                for (int j = 0; j < 8; j++)
                    acc[i][j] = fmaf(a[i], b[j], acc[i][j]);
        }
        __syncthreads();
    }

    // epilogue: add bias, write Sbuf
    #pragma unroll
    for (int i = 0; i < 8; i++) {
        int mm = m0 + ty * 8 + i;
        float* Crow = d_Sbuf + (size_t)mm * NG + n0;
        #pragma unroll
        for (int j = 0; j < 8; j++) {
            int nn = tx * 8 + j;
            Crow[nn] = acc[i][j] + d_Bcat[n0 + nn];
        }
    }
}

// ---------------- block reductions (blockDim = 512 = 16 warps) ----------------
__device__ __forceinline__ float warp_red_max(float v) {
    #pragma unroll
    for (int o = 16; o > 0; o >>= 1) v = fmaxf(v, __shfl_xor_sync(0xffffffffu, v, o));
    return v;
}
__device__ __forceinline__ float warp_red_sum(float v) {
    #pragma unroll
    for (int o = 16; o > 0; o >>= 1) v += __shfl_xor_sync(0xffffffffu, v, o);
    return v;
}
__device__ __forceinline__ float block_max(float v, float* sm) {
    __syncthreads();  // protect sm reuse from previous reduction
    v = warp_red_max(v);
    int w = threadIdx.x >> 5, l = threadIdx.x & 31;
    if (l == 0) sm[w] = v;
    __syncthreads();
    if (w == 0) {
        float x = (l < 16) ? sm[l] : -3.4e38f;
        x = warp_red_max(x);
        if (l == 0) sm[0] = x;
    }
    __syncthreads();
    return sm[0];
}
__device__ __forceinline__ float block_sum(float v, float* sm) {
    __syncthreads();
    v = warp_red_sum(v);
    int w = threadIdx.x >> 5, l = threadIdx.x & 31;
    if (l == 0) sm[w] = v;
    __syncthreads();
    if (w == 0) {
        float x = (l < 16) ? sm[l] : 0.0f;
        x = warp_red_sum(x);
        if (l == 0) sm[0] = x;
    }
    __syncthreads();
    return sm[0];
}
__device__ __forceinline__ float softmax_val(float s, float* sm) {
    float mx = block_max(s, sm);
    float e = expf(s - mx);
    float su = block_sum(e, sm);
    return e / su;
}

// ---------------- chain: sequential v-row recurrence over the wave ----------------
// v_{t+1}[h] = tanh(f_t[r][h]*v_t[h] + i_t[r][h]*g_t[r][h]),  r = (t+1) % P
__global__ void __launch_bounds__(512) chain_kernel(int t0, int nsteps) {
    __shared__ float sm[32];
    int h = threadIdx.x;
    float v = d_Vcarry[h];
    for (int j = 0; j < nsteps; j++) {
        d_Vbuf[j * H_DIM + h] = v;
        int r = (t0 + j + 1) % P_INT;
        const float* Srow = d_Sbuf + (size_t)(j * B_DIM + r) * NG;
        float f = softmax_val(Srow[h], sm);
        float i = softmax_val(Srow[H_DIM + h], sm);
        float g = tanhf(Srow[3 * H_DIM + h]);
        v = tanhf(f * v + i * g);
    }
    d_Vcarry[h] = v;
}

// ---------------- pointwise: per (step j, batch b): gates -> h[j][b][:] ----------------
__global__ void __launch_bounds__(512) pointwise_kernel() {
    __shared__ float sm[32];
    int m = blockIdx.x;        // j*512 + b
    int j = m >> 9;
    int h = threadIdx.x;
    const float* Srow = d_Sbuf + (size_t)m * NG;
    float f = softmax_val(Srow[h], sm);
    float i = softmax_val(Srow[H_DIM + h], sm);
    float o = softmax_val(Srow[2 * H_DIM + h], sm);
    float g = tanhf(Srow[3 * H_DIM + h]);
    float v = d_Vbuf[j * H_DIM + h];
    float cn = tanhf(f * v + i * g);
    d_Hbuf[(size_t)m * H_DIM + h] = o * cn;
}

// ---------------- output: h[(T-1) % P] = h[3] ----------------
__global__ void copy_out_kernel(float* __restrict__ out) {
    int i = blockIdx.x * blockDim.x + threadIdx.x;
    out[i] = d_Hbuf[3 * B_DIM * H_DIM + i];
}

// ---------------- launch ----------------
extern "C" void kernel_launch(void* const* d_in, const int* in_sizes, int n_in,
                              void* d_out, int out_size) {
    const float* x  = (const float*)d_in[0];
    const float* Wf = (const float*)d_in[1];
    const float* bf = (const float*)d_in[2];
    const float* Wi = (const float*)d_in[3];
    const float* bi = (const float*)d_in[4];
    const float* Wo = (const float*)d_in[5];
    const float* bo = (const float*)d_in[6];
    const float* Wg = (const float*)d_in[7];
    const float* bg = (const float*)d_in[8];
    float* out = (float*)d_out;

    {
        int n = KTOT * NG;
        pack_kernel<<<(n + 255) / 256, 256>>>(Wf, bf, Wi, bi, Wo, bo, Wg, bg);
    }
    {
        int n = P_INT * B_DIM * H_DIM;
        init_kernel<<<(n + 255) / 256, 256>>>();
    }

    int t0 = 0;
    while (t0 < T_LEN) {
        int ns = (T_LEN - t0 < P_INT) ? (T_LEN - t0) : P_INT;
        int M = ns * B_DIM;
        dim3 grid(NG / BN, M / BM);
        gemm_wave<<<grid, 256>>>(x, t0);
        chain_kernel<<<1, 512>>>(t0, ns);
        pointwise_kernel<<<M, 512>>>();
        t0 += ns;
    }

    copy_out_kernel<<<(B_DIM * H_DIM) / 256, 256>>>(out);
}

// round 3
// speedup vs baseline: 5.5372x; 5.5372x over previous
#include <cuda_runtime.h>
#include <cuda_fp16.h>
#include <cstdint>
#include <math.h>

#define T_LEN 256
#define B_DIM 512
#define F_DIM 256
#define H_DIM 512
#define P_INT 12
#define KTOT  768
#define NG    2048

// ---------------- GEMM tiling ----------------
#define BM 128
#define BN 128
#define BK 64              // halfs per stage (128 bytes per row)
#define STG 3
#define NCH (KTOT / BK)    // 12 K-chunks

#define A_SZ (BM * BK * 2) // 16384 B per stage
#define B_SZ (BN * BK * 2)
#define SMEM_BYTES (STG * (A_SZ + B_SZ))   // 96 KB

// ---------------- static device scratch ----------------
__device__ __half d_Wh[NG * KTOT];                // [2048][768] K-major fp16
__device__ float  d_Bcat[NG];
__device__ __half d_Xh[T_LEN * B_DIM * F_DIM];    // x in fp16
__device__ __half d_Hh[P_INT * B_DIM * H_DIM];    // h ring, fp16 (GEMM operand)
__device__ float  d_Hbuf[P_INT * B_DIM * H_DIM];  // h ring, fp32 (output fidelity)
__device__ float  d_Sbuf[P_INT * B_DIM * NG];     // wave pre-activations
__device__ float  d_Vbuf[P_INT * H_DIM];
__device__ float  d_Vcarry[H_DIM];

// ---------------- helpers ----------------
__device__ __forceinline__ uint32_t smem_u32(const void* p) {
    uint32_t a;
    asm("{ .reg .u64 t; cvta.to.shared.u64 t, %1; cvt.u32.u64 %0, t; }" : "=r"(a) : "l"(p));
    return a;
}
__device__ __forceinline__ void cpasync16(uint32_t dst, const void* src) {
    asm volatile("cp.async.cg.shared.global [%0], [%1], 16;"
                 :: "r"(dst), "l"(__cvta_generic_to_global(src)) : "memory");
}
__device__ __forceinline__ void ldm4(uint32_t* r, uint32_t addr) {
    asm volatile("ldmatrix.sync.aligned.m8n8.x4.shared.b16 {%0,%1,%2,%3}, [%4];"
                 : "=r"(r[0]), "=r"(r[1]), "=r"(r[2]), "=r"(r[3]) : "r"(addr));
}
__device__ __forceinline__ void mma16816(float* d, const uint32_t* a, uint32_t b0, uint32_t b1) {
    asm volatile(
        "mma.sync.aligned.m16n8k16.row.col.f32.f16.f16.f32 "
        "{%0,%1,%2,%3}, {%4,%5,%6,%7}, {%8,%9}, {%0,%1,%2,%3};"
        : "+f"(d[0]), "+f"(d[1]), "+f"(d[2]), "+f"(d[3])
        : "r"(a[0]), "r"(a[1]), "r"(a[2]), "r"(a[3]), "r"(b0), "r"(b1));
}

// ---------------- pack / convert / init ----------------
__global__ void pack_kernel(const float* __restrict__ Wf, const float* __restrict__ bf,
                            const float* __restrict__ Wi, const float* __restrict__ bi,
                            const float* __restrict__ Wo, const float* __restrict__ bo,
                            const float* __restrict__ Wg, const float* __restrict__ bg) {
    int idx = blockIdx.x * blockDim.x + threadIdx.x;
    if (idx < NG * KTOT) {
        int n = idx / KTOT;
        int k = idx % KTOT;
        int g = n >> 9, h = n & 511;
        const float* W = (g == 0) ? Wf : (g == 1) ? Wi : (g == 2) ? Wo : Wg;
        d_Wh[idx] = __float2half(W[k * H_DIM + h]);
    }
    if (idx < NG) {
        int g = idx / H_DIM, h = idx % H_DIM;
        const float* bb = (g == 0) ? bf : (g == 1) ? bi : (g == 2) ? bo : bg;
        d_Bcat[idx] = bb[h];
    }
}

__global__ void convx_kernel(const float* __restrict__ x) {
    int i = blockIdx.x * blockDim.x + threadIdx.x;
    d_Xh[i] = __float2half(x[i]);
}

__global__ void init_kernel() {
    int i = blockIdx.x * blockDim.x + threadIdx.x;
    if (i < P_INT * B_DIM * H_DIM) d_Hh[i] = __float2half(0.0f);
    if (i < H_DIM) d_Vcarry[i] = 0.0f;
}

// ---------------- stage loader ----------------
__device__ __forceinline__ void load_stage(uint32_t sa, uint32_t sbB, int tid, int ch,
                                           const __half* Xb, const __half* Hb, const __half* Wb) {
    const int k0 = ch * BK;
    const __half* asrc;
    int astride;
    if (k0 < F_DIM) { asrc = Xb + k0;           astride = F_DIM; }
    else            { asrc = Hb + (k0 - F_DIM); astride = H_DIM; }
    #pragma unroll
    for (int i = 0; i < 4; i++) {               // A: 128 rows x 8 chunks of 16B
        int cell = tid + i * 256;
        int r = cell >> 3, c = cell & 7;
        cpasync16(sa + r * 128 + ((c ^ (r & 7)) * 16),
                  asrc + (size_t)r * astride + c * 8);
    }
    #pragma unroll
    for (int i = 0; i < 4; i++) {               // B: 128 n-rows x 8 chunks
        int cell = tid + i * 256;
        int r = cell >> 3, c = cell & 7;
        cpasync16(sbB + r * 128 + ((c ^ (r & 7)) * 16),
                  Wb + (size_t)r * KTOT + k0 + c * 8);
    }
}

// ---------------- HMMA wave GEMM: Sbuf = A * W^T + bias ----------------
__global__ void __launch_bounds__(256, 2) gemm_hmma(int t0) {
    extern __shared__ char smem[];
    const uint32_t sb = smem_u32(smem);
    const int tid = threadIdx.x;
    const int wid = tid >> 5;
    const int l   = tid & 31;
    const int m0 = blockIdx.y * BM;
    const int n0 = blockIdx.x * BN;
    const int wm = (wid >> 2) * 64;   // warp m-offset (0,64)
    const int wn = (wid & 3) * 32;    // warp n-offset (0,32,64,96)

    const __half* Xb = d_Xh + ((size_t)t0 * B_DIM + m0) * F_DIM;
    const __half* Hb = d_Hh + (size_t)m0 * H_DIM;
    const __half* Wb = d_Wh + (size_t)n0 * KTOT;

    float acc[4][4][4];
    #pragma unroll
    for (int i = 0; i < 4; i++)
        #pragma unroll
        for (int j = 0; j < 4; j++)
            #pragma unroll
            for (int q = 0; q < 4; q++) acc[i][j][q] = 0.0f;

    uint32_t sA[STG], sB[STG];
    #pragma unroll
    for (int s = 0; s < STG; s++) {
        sA[s] = sb + s * (A_SZ + B_SZ);
        sB[s] = sA[s] + A_SZ;
    }

    // prologue: stages 0,1
    #pragma unroll
    for (int c = 0; c < STG - 1; c++) {
        load_stage(sA[c], sB[c], tid, c, Xb, Hb, Wb);
        asm volatile("cp.async.commit_group;" ::: "memory");
    }

    // ldmatrix lane addressing (row within tile, k-chunk select)
    const int lrow = l & 15;
    const int lk   = l >> 4;

    for (int ch = 0; ch < NCH; ch++) {
        asm volatile("cp.async.wait_group %0;" :: "n"(STG - 2) : "memory");
        __syncthreads();
        const int s = ch % STG;

        #pragma unroll
        for (int kk = 0; kk < BK / 16; kk++) {
            uint32_t af[4][4], bfr[2][4];
            #pragma unroll
            for (int mi = 0; mi < 4; mi++) {
                int r = wm + mi * 16 + lrow;
                int c = kk * 2 + lk;
                ldm4(af[mi], sA[s] + r * 128 + ((c ^ (r & 7)) * 16));
            }
            #pragma unroll
            for (int bj = 0; bj < 2; bj++) {
                int r = wn + bj * 16 + lrow;
                int c = kk * 2 + lk;
                ldm4(bfr[bj], sB[s] + r * 128 + ((c ^ (r & 7)) * 16));
            }
            #pragma unroll
            for (int mi = 0; mi < 4; mi++)
                #pragma unroll
                for (int nj = 0; nj < 4; nj++)
                    mma16816(acc[mi][nj], af[mi],
                             bfr[nj >> 1][nj & 1], bfr[nj >> 1][(nj & 1) + 2]);
        }
        __syncthreads();
        const int cl = ch + STG - 1;
        if (cl < NCH) {
            load_stage(sA[cl % STG], sB[cl % STG], tid, cl, Xb, Hb, Wb);
        }
        asm volatile("cp.async.commit_group;" ::: "memory");
    }

    // epilogue: bias + store fp32
    #pragma unroll
    for (int mi = 0; mi < 4; mi++) {
        #pragma unroll
        for (int nj = 0; nj < 4; nj++) {
            int m = m0 + wm + mi * 16 + (l >> 2);
            int n = n0 + wn + nj * 8 + (l & 3) * 2;
            float b0 = d_Bcat[n], b1 = d_Bcat[n + 1];
            float2 v0 = make_float2(acc[mi][nj][0] + b0, acc[mi][nj][1] + b1);
            float2 v1 = make_float2(acc[mi][nj][2] + b0, acc[mi][nj][3] + b1);
            *(float2*)(d_Sbuf + (size_t)m * NG + n) = v0;
            *(float2*)(d_Sbuf + (size_t)(m + 8) * NG + n) = v1;
        }
    }
}

// ---------------- warp softmax over 512 values (16 per lane) ----------------
__device__ __forceinline__ void softmax16(float* s) {
    float mx = -1e30f;
    #pragma unroll
    for (int q = 0; q < 16; q++) mx = fmaxf(mx, s[q]);
    #pragma unroll
    for (int o = 16; o > 0; o >>= 1) mx = fmaxf(mx, __shfl_xor_sync(0xffffffffu, mx, o));
    float sum = 0.0f;
    #pragma unroll
    for (int q = 0; q < 16; q++) { s[q] = __expf(s[q] - mx); sum += s[q]; }
    #pragma unroll
    for (int o = 16; o > 0; o >>= 1) sum += __shfl_xor_sync(0xffffffffu, sum, o);
    const float inv = 1.0f / sum;
    #pragma unroll
    for (int q = 0; q < 16; q++) s[q] *= inv;
}

// ---------------- chain: single warp, register-resident v recurrence ----------------
__global__ void chain_kernel(int t0, int ns) {
    const int l = threadIdx.x;
    float v[16];
    #pragma unroll
    for (int q = 0; q < 16; q++) v[q] = d_Vcarry[q * 32 + l];
    for (int j = 0; j < ns; j++) {
        #pragma unroll
        for (int q = 0; q < 16; q++) d_Vbuf[j * H_DIM + q * 32 + l] = v[q];
        const int r = (t0 + j + 1) % P_INT;
        const float* S = d_Sbuf + (size_t)(j * B_DIM + r) * NG;
        float sf[16], si[16], sg[16];
        #pragma unroll
        for (int q = 0; q < 16; q++) {
            sf[q] = S[q * 32 + l];
            si[q] = S[H_DIM + q * 32 + l];
            sg[q] = S[3 * H_DIM + q * 32 + l];
        }
        softmax16(sf);
        softmax16(si);
        #pragma unroll
        for (int q = 0; q < 16; q++)
            v[q] = tanhf(sf[q] * v[q] + si[q] * tanhf(sg[q]));
    }
    #pragma unroll
    for (int q = 0; q < 16; q++) d_Vcarry[q * 32 + l] = v[q];
}

// ---------------- pointwise: one warp per (step, batch) row ----------------
__global__ void __launch_bounds__(256) pointwise_kernel() {
    const int l = threadIdx.x & 31;
    const int m = (blockIdx.x * 256 + threadIdx.x) >> 5;
    const int j = m >> 9;
    const float* S = d_Sbuf + (size_t)m * NG;
    float sf[16], si[16], so[16], sg[16];
    #pragma unroll
    for (int q = 0; q < 16; q++) {
        sf[q] = S[q * 32 + l];
        si[q] = S[H_DIM + q * 32 + l];
        so[q] = S[2 * H_DIM + q * 32 + l];
        sg[q] = S[3 * H_DIM + q * 32 + l];
    }
    softmax16(sf);
    softmax16(si);
    softmax16(so);
    #pragma unroll
    for (int q = 0; q < 16; q++) {
        const float vv = d_Vbuf[j * H_DIM + q * 32 + l];
        const float cn = tanhf(sf[q] * vv + si[q] * tanhf(sg[q]));
        const float hv = so[q] * cn;
        d_Hbuf[(size_t)m * H_DIM + q * 32 + l] = hv;
        d_Hh[(size_t)m * H_DIM + q * 32 + l] = __float2half(hv);
    }
}

__global__ void copy_out_kernel(float* __restrict__ out) {
    int i = blockIdx.x * blockDim.x + threadIdx.x;
    out[i] = d_Hbuf[3 * B_DIM * H_DIM + i];
}

// ---------------- launch ----------------
extern "C" void kernel_launch(void* const* d_in, const int* in_sizes, int n_in,
                              void* d_out, int out_size) {
    const float* x  = (const float*)d_in[0];
    const float* Wf = (const float*)d_in[1];
    const float* bf = (const float*)d_in[2];
    const float* Wi = (const float*)d_in[3];
    const float* bi = (const float*)d_in[4];
    const float* Wo = (const float*)d_in[5];
    const float* bo = (const float*)d_in[6];
    const float* Wg = (const float*)d_in[7];
    const float* bg = (const float*)d_in[8];
    float* out = (float*)d_out;

    cudaFuncSetAttribute(gemm_hmma, cudaFuncAttributeMaxDynamicSharedMemorySize, SMEM_BYTES);

    {
        int n = NG * KTOT;
        pack_kernel<<<(n + 255) / 256, 256>>>(Wf, bf, Wi, bi, Wo, bo, Wg, bg);
    }
    {
        int n = T_LEN * B_DIM * F_DIM;
        convx_kernel<<<n / 256, 256>>>(x);
    }
    {
        int n = P_INT * B_DIM * H_DIM;
        init_kernel<<<(n + 255) / 256, 256>>>();
    }

    int t0 = 0;
    while (t0 < T_LEN) {
        const int ns = (T_LEN - t0 < P_INT) ? (T_LEN - t0) : P_INT;
        const int M = ns * B_DIM;
        dim3 grid(NG / BN, M / BM);
        gemm_hmma<<<grid, 256, SMEM_BYTES>>>(t0);
        chain_kernel<<<1, 32>>>(t0, ns);
        pointwise_kernel<<<M / 8, 256>>>();
        t0 += ns;
    }

    copy_out_kernel<<<(B_DIM * H_DIM) / 256, 256>>>(out);
}

// round 4
// speedup vs baseline: 5.6364x; 1.0179x over previous
#include <cuda_runtime.h>
#include <cuda_fp16.h>
#include <cstdint>
#include <math.h>

#define T_LEN 256
#define B_DIM 512
#define F_DIM 256
#define H_DIM 512
#define P_INT 12
#define KTOT  768
#define NG    2048

// ---------------- GEMM tiling ----------------
#define BM 128
#define BN 128
#define BK 64              // halfs per stage (128 bytes per row)
#define STG 3
#define NCH (KTOT / BK)    // 12 K-chunks
#define NTN (NG / BN)      // 16 n-tiles
#define GRID_G 296         // persistent CTAs (2 per SM on 148 SMs)

#define A_SZ (BM * BK * 2) // 16384 B per stage
#define B_SZ (BN * BK * 2)
#define SMEM_BYTES (STG * (A_SZ + B_SZ))   // 96 KB

// ---------------- static device scratch ----------------
__device__ __half d_Wh[NG * KTOT];                // [2048][768] K-major fp16
__device__ float  d_Bcat[NG];
__device__ __half d_Xh[T_LEN * B_DIM * F_DIM];    // x in fp16
__device__ __half d_Hh[P_INT * B_DIM * H_DIM];    // h ring, fp16 (GEMM operand)
__device__ float  d_Hout[B_DIM * H_DIM];          // fp32 h for ring slot 3 (output)
__device__ __half d_Sbuf[P_INT * B_DIM * NG];     // wave pre-activations, fp16
__device__ float  d_Vbuf[P_INT * H_DIM];
__device__ float  d_Vcarry[H_DIM];

// ---------------- helpers ----------------
__device__ __forceinline__ uint32_t smem_u32(const void* p) {
    uint32_t a;
    asm("{ .reg .u64 t; cvta.to.shared.u64 t, %1; cvt.u32.u64 %0, t; }" : "=r"(a) : "l"(p));
    return a;
}
__device__ __forceinline__ void cpasync16(uint32_t dst, const void* src) {
    asm volatile("cp.async.cg.shared.global [%0], [%1], 16;"
                 :: "r"(dst), "l"(__cvta_generic_to_global(src)) : "memory");
}
__device__ __forceinline__ void ldm4(uint32_t* r, uint32_t addr) {
    asm volatile("ldmatrix.sync.aligned.m8n8.x4.shared.b16 {%0,%1,%2,%3}, [%4];"
                 : "=r"(r[0]), "=r"(r[1]), "=r"(r[2]), "=r"(r[3]) : "r"(addr));
}
__device__ __forceinline__ void mma16816(float* d, const uint32_t* a, uint32_t b0, uint32_t b1) {
    asm volatile(
        "mma.sync.aligned.m16n8k16.row.col.f32.f16.f16.f32 "
        "{%0,%1,%2,%3}, {%4,%5,%6,%7}, {%8,%9}, {%0,%1,%2,%3};"
        : "+f"(d[0]), "+f"(d[1]), "+f"(d[2]), "+f"(d[3])
        : "r"(a[0]), "r"(a[1]), "r"(a[2]), "r"(a[3]), "r"(b0), "r"(b1));
}

// ---------------- pack / convert / init ----------------
__global__ void pack_kernel(const float* __restrict__ Wf, const float* __restrict__ bf,
                            const float* __restrict__ Wi, const float* __restrict__ bi,
                            const float* __restrict__ Wo, const float* __restrict__ bo,
                            const float* __restrict__ Wg, const float* __restrict__ bg) {
    int idx = blockIdx.x * blockDim.x + threadIdx.x;
    if (idx < NG * KTOT) {
        int n = idx / KTOT;
        int k = idx % KTOT;
        int g = n >> 9, h = n & 511;
        const float* W = (g == 0) ? Wf : (g == 1) ? Wi : (g == 2) ? Wo : Wg;
        d_Wh[idx] = __float2half(W[k * H_DIM + h]);
    }
    if (idx < NG) {
        int g = idx / H_DIM, h = idx % H_DIM;
        const float* bb = (g == 0) ? bf : (g == 1) ? bi : (g == 2) ? bo : bg;
        d_Bcat[idx] = bb[h];
    }
}

__global__ void convx_kernel(const float* __restrict__ x) {
    int i = blockIdx.x * blockDim.x + threadIdx.x;
    d_Xh[i] = __float2half(x[i]);
}

__global__ void init_kernel() {
    int i = blockIdx.x * blockDim.x + threadIdx.x;
    if (i < P_INT * B_DIM * H_DIM) d_Hh[i] = __float2half(0.0f);
    if (i < H_DIM) d_Vcarry[i] = 0.0f;
}

// ---------------- stage loader ----------------
__device__ __forceinline__ void load_stage(uint32_t sa, uint32_t sbB, int tid, int ch,
                                           const __half* Xb, const __half* Hb, const __half* Wb) {
    const int k0 = ch * BK;
    const __half* asrc;
    int astride;
    if (k0 < F_DIM) { asrc = Xb + k0;           astride = F_DIM; }
    else            { asrc = Hb + (k0 - F_DIM); astride = H_DIM; }
    #pragma unroll
    for (int i = 0; i < 4; i++) {               // A: 128 rows x 8 chunks of 16B
        int cell = tid + i * 256;
        int r = cell >> 3, c = cell & 7;
        cpasync16(sa + r * 128 + ((c ^ (r & 7)) * 16),
                  asrc + (size_t)r * astride + c * 8);
    }
    #pragma unroll
    for (int i = 0; i < 4; i++) {               // B: 128 n-rows x 8 chunks
        int cell = tid + i * 256;
        int r = cell >> 3, c = cell & 7;
        cpasync16(sbB + r * 128 + ((c ^ (r & 7)) * 16),
                  Wb + (size_t)r * KTOT + k0 + c * 8);
    }
}

// ---------------- HMMA wave GEMM (persistent): Sbuf = A * W^T + bias ----------------
__global__ void __launch_bounds__(256, 2) gemm_hmma(int t0, int M) {
    extern __shared__ char smem[];
    const uint32_t sb = smem_u32(smem);
    const int tid = threadIdx.x;
    const int wid = tid >> 5;
    const int l   = tid & 31;
    const int wm = (wid >> 2) * 64;   // warp m-offset (0,64)
    const int wn = (wid & 3) * 32;    // warp n-offset (0,32,64,96)
    const int lrow = l & 15;
    const int lk   = l >> 4;

    uint32_t sA[STG], sB[STG];
    #pragma unroll
    for (int s = 0; s < STG; s++) {
        sA[s] = sb + s * (A_SZ + B_SZ);
        sB[s] = sA[s] + A_SZ;
    }

    const int ntiles = (M / BM) * NTN;
    for (int idx = blockIdx.x; idx < ntiles; idx += gridDim.x) {
        const int m0 = (idx / NTN) * BM;
        const int n0 = (idx % NTN) * BN;

        const __half* Xb = d_Xh + ((size_t)t0 * B_DIM + m0) * F_DIM;
        const __half* Hb = d_Hh + (size_t)m0 * H_DIM;
        const __half* Wb = d_Wh + (size_t)n0 * KTOT;

        float acc[4][4][4];
        #pragma unroll
        for (int i = 0; i < 4; i++)
            #pragma unroll
            for (int j = 0; j < 4; j++)
                #pragma unroll
                for (int q = 0; q < 4; q++) acc[i][j][q] = 0.0f;

        __syncthreads();   // all warps done reading smem of previous tile

        // prologue: stages 0,1
        #pragma unroll
        for (int c = 0; c < STG - 1; c++) {
            load_stage(sA[c], sB[c], tid, c, Xb, Hb, Wb);
            asm volatile("cp.async.commit_group;" ::: "memory");
        }

        for (int ch = 0; ch < NCH; ch++) {
            asm volatile("cp.async.wait_group 1;" ::: "memory");
            __syncthreads();
            // issue next-stage loads BEFORE compute (overlaps with MMAs)
            const int cl = ch + STG - 1;
            if (cl < NCH)
                load_stage(sA[cl % STG], sB[cl % STG], tid, cl, Xb, Hb, Wb);
            asm volatile("cp.async.commit_group;" ::: "memory");

            const int s = ch % STG;
            #pragma unroll
            for (int kk = 0; kk < BK / 16; kk++) {
                uint32_t af[4][4], bfr[2][4];
                #pragma unroll
                for (int mi = 0; mi < 4; mi++) {
                    int r = wm + mi * 16 + lrow;
                    int c = kk * 2 + lk;
                    ldm4(af[mi], sA[s] + r * 128 + ((c ^ (r & 7)) * 16));
                }
                #pragma unroll
                for (int bj = 0; bj < 2; bj++) {
                    int r = wn + bj * 16 + lrow;
                    int c = kk * 2 + lk;
                    ldm4(bfr[bj], sB[s] + r * 128 + ((c ^ (r & 7)) * 16));
                }
                #pragma unroll
                for (int mi = 0; mi < 4; mi++)
                    #pragma unroll
                    for (int nj = 0; nj < 4; nj++)
                        mma16816(acc[mi][nj], af[mi],
                                 bfr[nj >> 1][nj & 1], bfr[nj >> 1][(nj & 1) + 2]);
            }
        }

        // epilogue: bias + store fp16
        __half2* S2 = (__half2*)d_Sbuf;
        #pragma unroll
        for (int mi = 0; mi < 4; mi++) {
            #pragma unroll
            for (int nj = 0; nj < 4; nj++) {
                int m = m0 + wm + mi * 16 + (l >> 2);
                int n = n0 + wn + nj * 8 + (l & 3) * 2;
                float b0 = d_Bcat[n], b1 = d_Bcat[n + 1];
                S2[((size_t)m * NG + n) >> 1] =
                    __floats2half2_rn(acc[mi][nj][0] + b0, acc[mi][nj][1] + b1);
                S2[((size_t)(m + 8) * NG + n) >> 1] =
                    __floats2half2_rn(acc[mi][nj][2] + b0, acc[mi][nj][3] + b1);
            }
        }
    }
}

// ---------------- warp softmax over 512 values (16 per lane) ----------------
__device__ __forceinline__ void softmax16(float* s) {
    float mx = -1e30f;
    #pragma unroll
    for (int q = 0; q < 16; q++) mx = fmaxf(mx, s[q]);
    #pragma unroll
    for (int o = 16; o > 0; o >>= 1) mx = fmaxf(mx, __shfl_xor_sync(0xffffffffu, mx, o));
    float sum = 0.0f;
    #pragma unroll
    for (int q = 0; q < 16; q++) { s[q] = __expf(s[q] - mx); sum += s[q]; }
    #pragma unroll
    for (int o = 16; o > 0; o >>= 1) sum += __shfl_xor_sync(0xffffffffu, sum, o);
    const float inv = 1.0f / sum;
    #pragma unroll
    for (int q = 0; q < 16; q++) s[q] *= inv;
}

// lane-value layout: element q (0..15) of lane l maps to index (q>>1)*64 + l*2 + (q&1)
__device__ __forceinline__ void load_gate16(const __half2* base, int l, float* s) {
    #pragma unroll
    for (int q2 = 0; q2 < 8; q2++) {
        float2 v = __half22float2(base[q2 * 32 + l]);
        s[2 * q2] = v.x;
        s[2 * q2 + 1] = v.y;
    }
}

// ---------------- chain: single warp, register-resident v recurrence ----------------
__global__ void chain_kernel(int t0, int ns) {
    const int l = threadIdx.x;
    float v[16];
    #pragma unroll
    for (int q2 = 0; q2 < 8; q2++) {
        float2 vc = *(const float2*)(d_Vcarry + q2 * 64 + l * 2);
        v[2 * q2] = vc.x;
        v[2 * q2 + 1] = vc.y;
    }
    for (int j = 0; j < ns; j++) {
        #pragma unroll
        for (int q2 = 0; q2 < 8; q2++)
            *(float2*)(d_Vbuf + j * H_DIM + q2 * 64 + l * 2) =
                make_float2(v[2 * q2], v[2 * q2 + 1]);
        const int r = (t0 + j + 1) % P_INT;
        const __half2* S = (const __half2*)d_Sbuf + (((size_t)(j * B_DIM + r) * NG) >> 1);
        float sf[16], si[16], sg[16];
        load_gate16(S, l, sf);
        load_gate16(S + (H_DIM >> 1), l, si);
        load_gate16(S + ((3 * H_DIM) >> 1), l, sg);
        softmax16(sf);
        softmax16(si);
        #pragma unroll
        for (int q = 0; q < 16; q++)
            v[q] = tanhf(sf[q] * v[q] + si[q] * tanhf(sg[q]));
    }
    #pragma unroll
    for (int q2 = 0; q2 < 8; q2++)
        *(float2*)(d_Vcarry + q2 * 64 + l * 2) = make_float2(v[2 * q2], v[2 * q2 + 1]);
}

// ---------------- pointwise: one warp per (step, batch) row ----------------
__global__ void __launch_bounds__(256) pointwise_kernel() {
    const int l = threadIdx.x & 31;
    const int m = (blockIdx.x * 256 + threadIdx.x) >> 5;
    const int j = m >> 9;
    const __half2* S = (const __half2*)d_Sbuf + (((size_t)m * NG) >> 1);
    float sf[16], si[16], so[16], sg[16];
    load_gate16(S, l, sf);
    load_gate16(S + (H_DIM >> 1), l, si);
    load_gate16(S + ((2 * H_DIM) >> 1), l, so);
    load_gate16(S + ((3 * H_DIM) >> 1), l, sg);
    softmax16(sf);
    softmax16(si);
    softmax16(so);
    __half2* Hh2 = (__half2*)d_Hh;
    const bool wout = (j == 3);   // ring slot 3 feeds the output
    #pragma unroll
    for (int q2 = 0; q2 < 8; q2++) {
        float2 vv = *(const float2*)(d_Vbuf + j * H_DIM + q2 * 64 + l * 2);
        float c0 = tanhf(sf[2 * q2] * vv.x + si[2 * q2] * tanhf(sg[2 * q2]));
        float c1 = tanhf(sf[2 * q2 + 1] * vv.y + si[2 * q2 + 1] * tanhf(sg[2 * q2 + 1]));
        float h0 = so[2 * q2] * c0;
        float h1 = so[2 * q2 + 1] * c1;
        Hh2[((size_t)m * H_DIM + q2 * 64 + l * 2) >> 1] = __floats2half2_rn(h0, h1);
        if (wout)
            *(float2*)(d_Hout + (size_t)(m & 511) * H_DIM + q2 * 64 + l * 2) =
                make_float2(h0, h1);
    }
}

__global__ void copy_out_kernel(float* __restrict__ out) {
    int i = blockIdx.x * blockDim.x + threadIdx.x;
    out[i] = d_Hout[i];
}

// ---------------- launch ----------------
extern "C" void kernel_launch(void* const* d_in, const int* in_sizes, int n_in,
                              void* d_out, int out_size) {
    const float* x  = (const float*)d_in[0];
    const float* Wf = (const float*)d_in[1];
    const float* bf = (const float*)d_in[2];
    const float* Wi = (const float*)d_in[3];
    const float* bi = (const float*)d_in[4];
    const float* Wo = (const float*)d_in[5];
    const float* bo = (const float*)d_in[6];
    const float* Wg = (const float*)d_in[7];
    const float* bg = (const float*)d_in[8];
    float* out = (float*)d_out;

    cudaFuncSetAttribute(gemm_hmma, cudaFuncAttributeMaxDynamicSharedMemorySize, SMEM_BYTES);

    {
        int n = NG * KTOT;
        pack_kernel<<<(n + 255) / 256, 256>>>(Wf, bf, Wi, bi, Wo, bo, Wg, bg);
    }
    {
        int n = T_LEN * B_DIM * F_DIM;
        convx_kernel<<<n / 256, 256>>>(x);
    }
    {
        int n = P_INT * B_DIM * H_DIM;
        init_kernel<<<(n + 255) / 256, 256>>>();
    }

    int t0 = 0;
    while (t0 < T_LEN) {
        const int ns = (T_LEN - t0 < P_INT) ? (T_LEN - t0) : P_INT;
        const int M = ns * B_DIM;
        gemm_hmma<<<GRID_G, 256, SMEM_BYTES>>>(t0, M);
        chain_kernel<<<1, 32>>>(t0, ns);
        pointwise_kernel<<<M / 8, 256>>>();
        t0 += ns;
    }

    copy_out_kernel<<<(B_DIM * H_DIM) / 256, 256>>>(out);
}